// round 14
// baseline (speedup 1.0000x reference)
#include <cuda_runtime.h>
#include <math.h>

#define Bdim 32
#define Tdim 1024
#define DIdim 512
#define Hdim 512
#define NG (4*Hdim)

#define HROW 516                       // padded h row (floats)
#define CLUSTER_N 8
#define H_SLICE_BYTES 8256u            // 4 rows * 516 * 4
#define H_HALF_BYTES  33024u           // 4 slices (16 rows)

// Scratch (device globals)
__device__ float    g_G[Tdim*Bdim*NG];        // [t][b][gate*512+j] = x@W + bias
__device__ unsigned g_A[Tdim*Bdim*DIdim];     // tf32(X) gathered, row m=t*32+b
__device__ unsigned g_Wt[DIdim*NG];           // tf32(W) fused [k][gate*512+c]
__device__ unsigned g_Ut[Hdim*NG];            // tf32(U) fused block-interleaved
__device__ float    g_bias[NG];
__device__ __align__(16) float g_h[2][32*HROW];  // tf32-valued h, PADDED, double-buffered
__device__ unsigned int g_bar;                // grid barrier counter

__device__ __forceinline__ unsigned f2tf32(float f) {
    unsigned r;
    asm("cvt.rna.tf32.f32 %0, %1;" : "=r"(r) : "f"(f));
    return r;
}

__device__ __forceinline__ void mma_tf32(float* d, const unsigned* a, const unsigned* b) {
    asm volatile(
        "mma.sync.aligned.m16n8k8.row.col.f32.tf32.tf32.f32 "
        "{%0,%1,%2,%3}, {%4,%5,%6,%7}, {%8,%9}, {%0,%1,%2,%3};"
        : "+f"(d[0]), "+f"(d[1]), "+f"(d[2]), "+f"(d[3])
        : "r"(a[0]), "r"(a[1]), "r"(a[2]), "r"(a[3]), "r"(b[0]), "r"(b[1]));
}

__device__ __forceinline__ float tanh_fast(float x) {
    float e = __expf(2.0f * x);
    return 1.0f - __fdividef(2.0f, e + 1.0f);   // inf-safe
}
__device__ __forceinline__ float sigmoid_fast(float x) {
    return __fdividef(1.0f, 1.0f + __expf(-x));
}

__device__ __forceinline__ void cp_async16(unsigned smem_dst, const void* gsrc) {
    asm volatile("cp.async.cg.shared.global [%0], [%1], 16;"
                 :: "r"(smem_dst), "l"(gsrc) : "memory");
}

// ---------------------------------------------------------------------------
__global__ void init_kernel(const float* __restrict__ init_states,
                            const float* __restrict__ bi, const float* __restrict__ bf,
                            const float* __restrict__ bc, const float* __restrict__ bo)
{
    int i = blockIdx.x * blockDim.x + threadIdx.x;
    if (i < Bdim*Hdim) {
        int b = i >> 9, j = i & 511;
        g_h[0][b*HROW + j] = __uint_as_float(f2tf32(init_states[i]));  // tf32-rounded h0
    }
    if (i < NG) {
        int gate = i >> 9, c = i & 511;
        const float* b = (gate==0) ? bi : (gate==1) ? bf : (gate==2) ? bc : bo;
        g_bias[i] = b[c];
    }
    if (i == 0) g_bar = 0u;
}

// ---------------------------------------------------------------------------
// Fused prep: blocks [0,16384) = X gather; [16384,17408) = W fuse;
// [17408,18432) = U fuse+interleave.
// ---------------------------------------------------------------------------
__global__ __launch_bounds__(256) void prep_all_kernel(
    const float* __restrict__ X,
    const float* __restrict__ Wi, const float* __restrict__ Wf,
    const float* __restrict__ Wc, const float* __restrict__ Wo,
    const float* __restrict__ Ui, const float* __restrict__ Uf,
    const float* __restrict__ Uc, const float* __restrict__ Uo)
{
    int bid = blockIdx.x;
    int tid = threadIdx.x;
    if (bid < 16384) {
        int idx = bid * 256 + tid;
        int m  = idx >> 7;
        int k4 = idx & 127;
        int b = m & 31, t = m >> 5;
        float4 v = *(const float4*)(X + ((size_t)b * Tdim + t) * DIdim + k4*4);
        uint4 o;
        o.x = f2tf32(v.x); o.y = f2tf32(v.y); o.z = f2tf32(v.z); o.w = f2tf32(v.w);
        *(uint4*)(g_A + (size_t)m * DIdim + k4*4) = o;
    } else if (bid < 17408) {
        int idx = (bid - 16384) * 256 + tid;
        int gate = idx >> 16;
        int rem  = idx & 65535;
        int k  = rem >> 7;
        int c4 = rem & 127;
        const float* W = (gate==0) ? Wi : (gate==1) ? Wf : (gate==2) ? Wc : Wo;
        float4 v = *(const float4*)(W + (size_t)k * Hdim + c4*4);
        uint4 o;
        o.x = f2tf32(v.x); o.y = f2tf32(v.y); o.z = f2tf32(v.z); o.w = f2tf32(v.w);
        *(uint4*)(g_Wt + (size_t)k * NG + gate*512 + c4*4) = o;
    } else {
        int idx = (bid - 17408) * 256 + tid;
        int gate = idx >> 16;
        int rem  = idx & 65535;
        int k  = rem >> 7;
        int jq = rem & 127;
        const float* U = (gate==0) ? Ui : (gate==1) ? Uf : (gate==2) ? Uc : Uo;
        float4 v = *(const float4*)(U + (size_t)k * Hdim + jq*4);
        uint4 o;
        o.x = f2tf32(v.x); o.y = f2tf32(v.y); o.z = f2tf32(v.z); o.w = f2tf32(v.w);
        *(uint4*)(g_Ut + (size_t)k * NG + jq*16 + gate*4) = o;
    }
}

// ---------------------------------------------------------------------------
// xw GEMM, 128x128 CTA tile + 2-stage cp.async pipeline (verified round 12).
// ---------------------------------------------------------------------------
#define AS_PAD 36
#define BS_PAD 132
#define XW_STAGE_A (128*AS_PAD)
#define XW_STAGE_B (32*BS_PAD)
#define XW_STAGE   (XW_STAGE_A + XW_STAGE_B)
#define XW_SMEM_BYTES (2*XW_STAGE*4)      // 70656 B

__global__ __launch_bounds__(256) void xw_mma_kernel() {
    extern __shared__ unsigned smx[];

    const int tid = threadIdx.x;
    const int wid = tid >> 5;
    const int lane = tid & 31;
    const int gid = lane >> 2;
    const int tig = lane & 3;

    const int warp_m = (wid & 3) * 32;
    const int warp_n = (wid >> 2) * 64;

    const int mbase = blockIdx.x * 128;
    const int nbase = blockIdx.y * 128;

    unsigned smem_u32;
    asm("{ .reg .u64 t0; cvta.to.shared.u64 t0, %1; cvt.u32.u64 %0, t0; }"
        : "=r"(smem_u32) : "l"(smx));

    const int a_row[4] = { (tid)>>3, (tid+256)>>3, (tid+512)>>3, (tid+768)>>3 };
    const int a_k4  = (tid & 7) * 4;
    const int b_krow[4] = { tid>>5, (tid+256)>>5, (tid+512)>>5, (tid+768)>>5 };
    const int b_n4  = (tid & 31) * 4;

    auto issue_chunk = [&](int k0, int s) {
        unsigned base = smem_u32 + s * XW_STAGE * 4;
        #pragma unroll
        for (int r = 0; r < 4; r++) {
            const void* src = g_A + (size_t)(mbase + a_row[r]) * DIdim + k0 + a_k4;
            cp_async16(base + (a_row[r]*AS_PAD + a_k4)*4, src);
        }
        #pragma unroll
        for (int r = 0; r < 4; r++) {
            const void* src = g_Wt + (size_t)(k0 + b_krow[r]) * NG + nbase + b_n4;
            cp_async16(base + (XW_STAGE_A + b_krow[r]*BS_PAD + b_n4)*4, src);
        }
        asm volatile("cp.async.commit_group;" ::: "memory");
    };

    float acc[2][8][4];
    #pragma unroll
    for (int mt = 0; mt < 2; mt++)
        #pragma unroll
        for (int nt = 0; nt < 8; nt++)
            #pragma unroll
            for (int r = 0; r < 4; r++) acc[mt][nt][r] = 0.f;

    issue_chunk(0, 0);

    for (int i = 0; i < 16; i++) {
        if (i < 15) {
            issue_chunk((i+1)*32, (i+1) & 1);
            asm volatile("cp.async.wait_group 1;" ::: "memory");
        } else {
            asm volatile("cp.async.wait_group 0;" ::: "memory");
        }
        __syncthreads();

        const unsigned* As = smx + (i & 1) * XW_STAGE;
        const unsigned* Bs = As + XW_STAGE_A;

        #pragma unroll
        for (int ks = 0; ks < 4; ks++) {
            const int k8 = ks * 8;
            unsigned af[2][4];
            #pragma unroll
            for (int mt = 0; mt < 2; mt++) {
                int row = warp_m + mt*16 + gid;
                af[mt][0] = As[(row    ) * AS_PAD + k8 + tig    ];
                af[mt][1] = As[(row + 8) * AS_PAD + k8 + tig    ];
                af[mt][2] = As[(row    ) * AS_PAD + k8 + tig + 4];
                af[mt][3] = As[(row + 8) * AS_PAD + k8 + tig + 4];
            }
            unsigned bf2[8][2];
            #pragma unroll
            for (int nt = 0; nt < 8; nt++) {
                int col = warp_n + nt*8 + gid;
                bf2[nt][0] = Bs[(k8 + tig    ) * BS_PAD + col];
                bf2[nt][1] = Bs[(k8 + tig + 4) * BS_PAD + col];
            }
            #pragma unroll
            for (int mt = 0; mt < 2; mt++)
                #pragma unroll
                for (int nt = 0; nt < 8; nt++)
                    mma_tf32(acc[mt][nt], af[mt], bf2[nt]);
        }
        __syncthreads();
    }

    #pragma unroll
    for (int mt = 0; mt < 2; mt++) {
        #pragma unroll
        for (int nt = 0; nt < 8; nt++) {
            int col = nbase + warp_n + nt*8 + 2*tig;
            float b0 = g_bias[col];
            float b1 = g_bias[col + 1];
            int row0 = mbase + warp_m + mt*16 + gid;
            float2 o0 = make_float2(acc[mt][nt][0] + b0, acc[mt][nt][1] + b1);
            float2 o1 = make_float2(acc[mt][nt][2] + b0, acc[mt][nt][3] + b1);
            *(float2*)(g_G + (size_t)row0 * NG + col)       = o0;
            *(float2*)(g_G + (size_t)(row0 + 8) * NG + col) = o1;
        }
    }
}

// ---------------------------------------------------------------------------
// Persistent tensor-core recurrence. 128 CTAs x 256 threads, CLUSTERS OF 8
// (TMA multicast dedup: csz=8 halves L2 read traffic of the h all-gather;
// csz<=4 gets none per B300 measurements). 8 slices of 4 rows; ranks 0-3
// signal mbar0 (rows 0-15), ranks 4-7 signal mbar1 (rows 16-31).
// Barrier: round-12 single-atomic (measured best; r7/r13 alternatives lost).
// TMA for step t+1 issued by the poller the moment release is detected.
// ---------------------------------------------------------------------------
#define SH_H 0
#define SH_P 16512                       // floats (== 32*516)
#define SH_TOTAL (SH_P + 8*290)          // floats
#define SMEM_BYTES (SH_TOTAL*4 + 16)     // + two mbarriers

__global__ __launch_bounds__(256,1) __cluster_dims__(CLUSTER_N,1,1)
void lstm_kernel(const float* __restrict__ init_states,
                 float* __restrict__ out)
{
    extern __shared__ __align__(16) float smf[];

    const int tid  = threadIdx.x;
    const int w    = tid >> 5;
    const int lane = tid & 31;
    const int gid  = lane >> 2;
    const int tig  = lane & 3;
    const int kh   = w & 3;        // k-quarter (128 k each)
    const int mt   = w >> 2;       // m-tile (16 batches each)
    const int jb   = blockIdx.x * 4;
    const int kbase = kh * 128;

    unsigned smem_u32;
    asm("{ .reg .u64 t0; cvta.to.shared.u64 t0, %1; cvt.u32.u64 %0, t0; }"
        : "=r"(smem_u32) : "l"(smf));
    const unsigned mbar0 = smem_u32 + SH_TOTAL*4;
    const unsigned mbar1 = mbar0 + 8;
    const unsigned my_wait_mbar = mt ? mbar1 : mbar0;

    unsigned rank;
    asm("mov.u32 %0, %%cluster_ctarank;" : "=r"(rank));
    const unsigned my_tma_mbar = (rank >= 4) ? mbar1 : mbar0;

    // --- preload U fragments into registers (once): ub[nt][ks][2] ---
    unsigned ub[2][16][2];
    {
        #pragma unroll
        for (int nt = 0; nt < 2; nt++) {
            const unsigned* Ucol = g_Ut + (size_t)kbase * NG + blockIdx.x*16 + nt*8 + gid;
            #pragma unroll
            for (int ks = 0; ks < 16; ks++) {
                ub[nt][ks][0] = Ucol[(size_t)(ks*8 + tig    ) * NG];
                ub[nt][ks][1] = Ucol[(size_t)(ks*8 + tig + 4) * NG];
            }
        }
    }

    // owner mapping (tid < 128): one (batch, jj) cell each
    const int o_b  = tid >> 2;     // 0..31
    const int o_jj = tid & 3;
    const int o_mt = o_b >> 4;
    const int o_row = o_b & 15;
    float cstate = 0.f;
    if (tid < 128) cstate = init_states[Bdim*Hdim + o_b*Hdim + jb + o_jj];

    // mbarrier init + cluster sync (peers' multicast needs my mbars live)
    if (tid == 0) {
        asm volatile("mbarrier.init.shared.b64 [%0], 1;" :: "r"(mbar0) : "memory");
        asm volatile("mbarrier.init.shared.b64 [%0], 1;" :: "r"(mbar1) : "memory");
    }
    __syncthreads();
    asm volatile("barrier.cluster.arrive.aligned;" ::: "memory");
    asm volatile("barrier.cluster.wait.aligned;" ::: "memory");

    // helper to issue this CTA's slice of h[buf] with expect_tx for the step
    auto issue_h_tma = [&](int buf) {
        asm volatile("mbarrier.arrive.expect_tx.shared.b64 _, [%0], %1;"
                     :: "r"(mbar0), "r"(H_HALF_BYTES) : "memory");
        asm volatile("mbarrier.arrive.expect_tx.shared.b64 _, [%0], %1;"
                     :: "r"(mbar1), "r"(H_HALF_BYTES) : "memory");
        const char* src = (const char*)(g_h[buf]) + rank * H_SLICE_BYTES;
        unsigned dst = smem_u32 + rank * H_SLICE_BYTES;
        asm volatile(
            "cp.async.bulk.shared::cluster.global.mbarrier::complete_tx::bytes.multicast::cluster "
            "[%0], [%1], %2, [%3], %4;"
            :: "r"(dst), "l"(src), "r"(H_SLICE_BYTES), "r"(my_tma_mbar),
               "h"((unsigned short)0xFF) : "memory");
    };

    // prime step 0
    if (tid == 0) issue_h_tma(0);

    float hn = 0.f;   // carried for deferred out-store

    for (int t = 0; t < Tdim; t++) {
        // prefetch G (DRAM; consumed after mma+reduce) — overlaps TMA
        float pg0=0.f, pg1=0.f, pg2=0.f, pg3=0.f;
        if (tid < 128) {
            const float* gr = g_G + ((size_t)t * Bdim + o_b) * NG + jb + o_jj;
            pg0 = __ldcg(gr);
            pg1 = __ldcg(gr + 512);
            pg2 = __ldcg(gr + 1024);
            pg3 = __ldcg(gr + 1536);
        }

        // wait only for my half (warps mt=0: batches 0-15; mt=1: 16-31)
        {
            unsigned parity = t & 1;
            asm volatile(
                "{\n\t.reg .pred P;\n"
                "W%=:\n\t"
                "mbarrier.try_wait.parity.acquire.cta.shared::cta.b64 P, [%0], %1, 0x989680;\n\t"
                "@P bra D%=;\n\t"
                "bra W%=;\n"
                "D%=:\n\t}"
                :: "r"(my_wait_mbar), "r"(parity) : "memory");
        }

        // mma: warp tile m16 x n16, K=128; 4 sub-chains (2 nt x even/odd ks)
        float acc0[2][4], acc1[2][4];
        #pragma unroll
        for (int nt = 0; nt < 2; nt++)
            #pragma unroll
            for (int r = 0; r < 4; r++) { acc0[nt][r] = 0.f; acc1[nt][r] = 0.f; }
        {
            const int row = mt*16 + gid;
            const unsigned* hs = (const unsigned*)&smf[SH_H + row*HROW + kbase + tig];
            #pragma unroll
            for (int ks = 0; ks < 16; ks += 2) {
                unsigned afA[4], afB[4];
                afA[0] = hs[ks*8];
                afA[1] = hs[ks*8 + 8*HROW];
                afA[2] = hs[ks*8 + 4];
                afA[3] = hs[ks*8 + 8*HROW + 4];
                afB[0] = hs[(ks+1)*8];
                afB[1] = hs[(ks+1)*8 + 8*HROW];
                afB[2] = hs[(ks+1)*8 + 4];
                afB[3] = hs[(ks+1)*8 + 8*HROW + 4];
                mma_tf32(acc0[0], afA, ub[0][ks]);
                mma_tf32(acc0[1], afA, ub[1][ks]);
                mma_tf32(acc1[0], afB, ub[0][ks+1]);
                mma_tf32(acc1[1], afB, ub[1][ks+1]);
            }
        }

        // stash merged partials: pbuf[w][row16][n16] (row stride 18, blk 290)
        {
            float* pb = &smf[SH_P + w*290];
            #pragma unroll
            for (int nt = 0; nt < 2; nt++) {
                *(float2*)&pb[ gid     *18 + nt*8 + 2*tig] =
                    make_float2(acc0[nt][0] + acc1[nt][0], acc0[nt][1] + acc1[nt][1]);
                *(float2*)&pb[(gid + 8)*18 + nt*8 + 2*tig] =
                    make_float2(acc0[nt][2] + acc1[nt][2], acc0[nt][3] + acc1[nt][3]);
            }
        }
        __syncthreads();

        // owners: 4-way k-reduce + G + LSTM cell; write tf32-rounded h
        if (tid < 128) {
            const float* pb = &smf[SH_P + (o_mt*4)*290 + o_row*18 + o_jj];
            float z0 = pg0, z1 = pg1, z2 = pg2, z3 = pg3;
            #pragma unroll
            for (int q = 0; q < 4; q++) {
                const float* r = pb + q*290;
                z0 += r[0];    // i
                z1 += r[4];    // f
                z2 += r[8];    // g
                z3 += r[12];   // o
            }
            float iv = sigmoid_fast(z0);
            float fv = sigmoid_fast(z1);
            float gv = tanh_fast(z2);
            float ov = sigmoid_fast(z3);
            cstate = fv * cstate + iv * gv;
            hn = ov * tanh_fast(cstate);
            g_h[(t+1) & 1][o_b*HROW + jb + o_jj] = __uint_as_float(f2tf32(hn));
        }
        __syncthreads();    // all h stores done (CTA scope)

        // ---- grid barrier: ONE fence + one atomic arrive per CTA ----
        if (tid == 0) {
            asm volatile("membar.gl;" ::: "memory");
            atomicAdd(&g_bar, 1u);
        }

        // deferred out store (full-precision hn) overlaps the barrier wait
        if (tid < 128) {
            out[((size_t)o_b * Tdim + t) * Hdim + jb + o_jj] = hn;
        }

        if (tid == 0) {
            unsigned target = (unsigned)gridDim.x * (unsigned)(t + 1);
            unsigned v;
            do {
                asm volatile("ld.acquire.gpu.global.u32 %0, [%1];"
                             : "=r"(v) : "l"(&g_bar) : "memory");
            } while (v < target);
            // issue next step's h gather IMMEDIATELY on release detection
            // (all CTAs' mma reads of SH_H finished before their arrivals)
            if (t + 1 < Tdim) issue_h_tma((t + 1) & 1);
        }
        __syncthreads();
    }

    asm volatile("barrier.cluster.arrive.aligned;" ::: "memory");
    asm volatile("barrier.cluster.wait.aligned;" ::: "memory");
}

// ---------------------------------------------------------------------------
extern "C" void kernel_launch(void* const* d_in, const int* in_sizes, int n_in,
                              void* d_out, int out_size) {
    const float* X           = (const float*)d_in[0];
    const float* init_states = (const float*)d_in[1];
    const float* Wi = (const float*)d_in[2];
    const float* Ui = (const float*)d_in[3];
    const float* bi = (const float*)d_in[4];
    const float* Wf = (const float*)d_in[5];
    const float* Uf = (const float*)d_in[6];
    const float* bf = (const float*)d_in[7];
    const float* Wc = (const float*)d_in[8];
    const float* Uc = (const float*)d_in[9];
    const float* bc = (const float*)d_in[10];
    const float* Wo = (const float*)d_in[11];
    const float* Uo = (const float*)d_in[12];
    const float* bo = (const float*)d_in[13];
    float* out = (float*)d_out;

    cudaFuncSetAttribute(lstm_kernel, cudaFuncAttributeMaxDynamicSharedMemorySize,
                         SMEM_BYTES);
    cudaFuncSetAttribute(xw_mma_kernel, cudaFuncAttributeMaxDynamicSharedMemorySize,
                         XW_SMEM_BYTES);

    init_kernel<<<(Bdim*Hdim + 255)/256, 256>>>(init_states, bi, bf, bc, bo);

    prep_all_kernel<<<16384 + 1024 + 1024, 256>>>(X, Wi, Wf, Wc, Wo, Ui, Uf, Uc, Uo);

    dim3 gemm_grid((Bdim*Tdim)/128, NG/128);   // (256, 16)
    xw_mma_kernel<<<gemm_grid, 256, XW_SMEM_BYTES>>>();

    lstm_kernel<<<128, 256, SMEM_BYTES>>>(init_states, out);
}

// round 15
// speedup vs baseline: 1.2009x; 1.2009x over previous
#include <cuda_runtime.h>
#include <math.h>

#define Bdim 32
#define Tdim 1024
#define DIdim 512
#define Hdim 512
#define NG (4*Hdim)

#define HROW 516                       // padded h row (floats)
#define H_SLICE_BYTES 16512u           // 8 rows * 516 * 4 (cluster of 4)
#define H_HALF_BYTES  33024u           // 2 slices (16 rows)

// Scratch (device globals)
__device__ float    g_G[Tdim*Bdim*NG];        // [t][b][gate*512+j] = x@W + bias
__device__ unsigned g_A[Tdim*Bdim*DIdim];     // tf32(X) gathered, row m=t*32+b
__device__ unsigned g_Wt[DIdim*NG];           // tf32(W) fused [k][gate*512+c]
__device__ unsigned g_Ut[Hdim*NG];            // tf32(U) fused block-interleaved
__device__ float    g_bias[NG];
__device__ __align__(16) float g_h[2][32*HROW];  // tf32-valued h, PADDED, double-buffered
__device__ unsigned int g_bar;                // grid barrier counter

__device__ __forceinline__ unsigned f2tf32(float f) {
    unsigned r;
    asm("cvt.rna.tf32.f32 %0, %1;" : "=r"(r) : "f"(f));
    return r;
}

__device__ __forceinline__ void mma_tf32(float* d, const unsigned* a, const unsigned* b) {
    asm volatile(
        "mma.sync.aligned.m16n8k8.row.col.f32.tf32.tf32.f32 "
        "{%0,%1,%2,%3}, {%4,%5,%6,%7}, {%8,%9}, {%0,%1,%2,%3};"
        : "+f"(d[0]), "+f"(d[1]), "+f"(d[2]), "+f"(d[3])
        : "r"(a[0]), "r"(a[1]), "r"(a[2]), "r"(a[3]), "r"(b[0]), "r"(b[1]));
}

__device__ __forceinline__ float tanh_fast(float x) {
    float e = __expf(2.0f * x);
    return 1.0f - __fdividef(2.0f, e + 1.0f);   // inf-safe
}
__device__ __forceinline__ float sigmoid_fast(float x) {
    return __fdividef(1.0f, 1.0f + __expf(-x));
}

__device__ __forceinline__ void cp_async16(unsigned smem_dst, const void* gsrc) {
    asm volatile("cp.async.cg.shared.global [%0], [%1], 16;"
                 :: "r"(smem_dst), "l"(gsrc) : "memory");
}

// ---------------------------------------------------------------------------
__global__ void init_kernel(const float* __restrict__ init_states,
                            const float* __restrict__ bi, const float* __restrict__ bf,
                            const float* __restrict__ bc, const float* __restrict__ bo)
{
    int i = blockIdx.x * blockDim.x + threadIdx.x;
    if (i < Bdim*Hdim) {
        int b = i >> 9, j = i & 511;
        g_h[0][b*HROW + j] = __uint_as_float(f2tf32(init_states[i]));  // tf32-rounded h0
    }
    if (i < NG) {
        int gate = i >> 9, c = i & 511;
        const float* b = (gate==0) ? bi : (gate==1) ? bf : (gate==2) ? bc : bo;
        g_bias[i] = b[c];
    }
    if (i == 0) g_bar = 0u;
}

// ---------------------------------------------------------------------------
// Fused prep: blocks [0,16384) = X gather; [16384,17408) = W fuse;
// [17408,18432) = U fuse+interleave.
// ---------------------------------------------------------------------------
__global__ __launch_bounds__(256) void prep_all_kernel(
    const float* __restrict__ X,
    const float* __restrict__ Wi, const float* __restrict__ Wf,
    const float* __restrict__ Wc, const float* __restrict__ Wo,
    const float* __restrict__ Ui, const float* __restrict__ Uf,
    const float* __restrict__ Uc, const float* __restrict__ Uo)
{
    int bid = blockIdx.x;
    int tid = threadIdx.x;
    if (bid < 16384) {
        int idx = bid * 256 + tid;
        int m  = idx >> 7;
        int k4 = idx & 127;
        int b = m & 31, t = m >> 5;
        float4 v = *(const float4*)(X + ((size_t)b * Tdim + t) * DIdim + k4*4);
        uint4 o;
        o.x = f2tf32(v.x); o.y = f2tf32(v.y); o.z = f2tf32(v.z); o.w = f2tf32(v.w);
        *(uint4*)(g_A + (size_t)m * DIdim + k4*4) = o;
    } else if (bid < 17408) {
        int idx = (bid - 16384) * 256 + tid;
        int gate = idx >> 16;
        int rem  = idx & 65535;
        int k  = rem >> 7;
        int c4 = rem & 127;
        const float* W = (gate==0) ? Wi : (gate==1) ? Wf : (gate==2) ? Wc : Wo;
        float4 v = *(const float4*)(W + (size_t)k * Hdim + c4*4);
        uint4 o;
        o.x = f2tf32(v.x); o.y = f2tf32(v.y); o.z = f2tf32(v.z); o.w = f2tf32(v.w);
        *(uint4*)(g_Wt + (size_t)k * NG + gate*512 + c4*4) = o;
    } else {
        int idx = (bid - 17408) * 256 + tid;
        int gate = idx >> 16;
        int rem  = idx & 65535;
        int k  = rem >> 7;
        int jq = rem & 127;
        const float* U = (gate==0) ? Ui : (gate==1) ? Uf : (gate==2) ? Uc : Uo;
        float4 v = *(const float4*)(U + (size_t)k * Hdim + jq*4);
        uint4 o;
        o.x = f2tf32(v.x); o.y = f2tf32(v.y); o.z = f2tf32(v.z); o.w = f2tf32(v.w);
        *(uint4*)(g_Ut + (size_t)k * NG + jq*16 + gate*4) = o;
    }
}

// ---------------------------------------------------------------------------
// xw GEMM, 128x128 CTA tile + 2-stage cp.async pipeline (verified round 12).
// ---------------------------------------------------------------------------
#define AS_PAD 36
#define BS_PAD 132
#define XW_STAGE_A (128*AS_PAD)
#define XW_STAGE_B (32*BS_PAD)
#define XW_STAGE   (XW_STAGE_A + XW_STAGE_B)
#define XW_SMEM_BYTES (2*XW_STAGE*4)      // 70656 B

__global__ __launch_bounds__(256) void xw_mma_kernel() {
    extern __shared__ unsigned smx[];

    const int tid = threadIdx.x;
    const int wid = tid >> 5;
    const int lane = tid & 31;
    const int gid = lane >> 2;
    const int tig = lane & 3;

    const int warp_m = (wid & 3) * 32;
    const int warp_n = (wid >> 2) * 64;

    const int mbase = blockIdx.x * 128;
    const int nbase = blockIdx.y * 128;

    unsigned smem_u32;
    asm("{ .reg .u64 t0; cvta.to.shared.u64 t0, %1; cvt.u32.u64 %0, t0; }"
        : "=r"(smem_u32) : "l"(smx));

    const int a_row[4] = { (tid)>>3, (tid+256)>>3, (tid+512)>>3, (tid+768)>>3 };
    const int a_k4  = (tid & 7) * 4;
    const int b_krow[4] = { tid>>5, (tid+256)>>5, (tid+512)>>5, (tid+768)>>5 };
    const int b_n4  = (tid & 31) * 4;

    auto issue_chunk = [&](int k0, int s) {
        unsigned base = smem_u32 + s * XW_STAGE * 4;
        #pragma unroll
        for (int r = 0; r < 4; r++) {
            const void* src = g_A + (size_t)(mbase + a_row[r]) * DIdim + k0 + a_k4;
            cp_async16(base + (a_row[r]*AS_PAD + a_k4)*4, src);
        }
        #pragma unroll
        for (int r = 0; r < 4; r++) {
            const void* src = g_Wt + (size_t)(k0 + b_krow[r]) * NG + nbase + b_n4;
            cp_async16(base + (XW_STAGE_A + b_krow[r]*BS_PAD + b_n4)*4, src);
        }
        asm volatile("cp.async.commit_group;" ::: "memory");
    };

    float acc[2][8][4];
    #pragma unroll
    for (int mt = 0; mt < 2; mt++)
        #pragma unroll
        for (int nt = 0; nt < 8; nt++)
            #pragma unroll
            for (int r = 0; r < 4; r++) acc[mt][nt][r] = 0.f;

    issue_chunk(0, 0);

    for (int i = 0; i < 16; i++) {
        if (i < 15) {
            issue_chunk((i+1)*32, (i+1) & 1);
            asm volatile("cp.async.wait_group 1;" ::: "memory");
        } else {
            asm volatile("cp.async.wait_group 0;" ::: "memory");
        }
        __syncthreads();

        const unsigned* As = smx + (i & 1) * XW_STAGE;
        const unsigned* Bs = As + XW_STAGE_A;

        #pragma unroll
        for (int ks = 0; ks < 4; ks++) {
            const int k8 = ks * 8;
            unsigned af[2][4];
            #pragma unroll
            for (int mt = 0; mt < 2; mt++) {
                int row = warp_m + mt*16 + gid;
                af[mt][0] = As[(row    ) * AS_PAD + k8 + tig    ];
                af[mt][1] = As[(row + 8) * AS_PAD + k8 + tig    ];
                af[mt][2] = As[(row    ) * AS_PAD + k8 + tig + 4];
                af[mt][3] = As[(row + 8) * AS_PAD + k8 + tig + 4];
            }
            unsigned bf2[8][2];
            #pragma unroll
            for (int nt = 0; nt < 8; nt++) {
                int col = warp_n + nt*8 + gid;
                bf2[nt][0] = Bs[(k8 + tig    ) * BS_PAD + col];
                bf2[nt][1] = Bs[(k8 + tig + 4) * BS_PAD + col];
            }
            #pragma unroll
            for (int mt = 0; mt < 2; mt++)
                #pragma unroll
                for (int nt = 0; nt < 8; nt++)
                    mma_tf32(acc[mt][nt], af[mt], bf2[nt]);
        }
        __syncthreads();
    }

    #pragma unroll
    for (int mt = 0; mt < 2; mt++) {
        #pragma unroll
        for (int nt = 0; nt < 8; nt++) {
            int col = nbase + warp_n + nt*8 + 2*tig;
            float b0 = g_bias[col];
            float b1 = g_bias[col + 1];
            int row0 = mbase + warp_m + mt*16 + gid;
            float2 o0 = make_float2(acc[mt][nt][0] + b0, acc[mt][nt][1] + b1);
            float2 o1 = make_float2(acc[mt][nt][2] + b0, acc[mt][nt][3] + b1);
            *(float2*)(g_G + (size_t)row0 * NG + col)       = o0;
            *(float2*)(g_G + (size_t)(row0 + 8) * NG + col) = o1;
        }
    }
}

// ---------------------------------------------------------------------------
// Persistent tensor-core recurrence — EXACT round-12 structure (measured
// best, 2999us: cluster=4 multicast, 2-mbar pipelined halves, single-atomic
// barrier) with ONE change: the next step's h-TMA is issued by the poller
// thread the instant release is detected (t=0 primed before the loop),
// removing the post-barrier bar.sync + loop re-entry from the TMA's
// critical path. r14's cluster=8 is REVERTED (latency regression, +542us).
// ---------------------------------------------------------------------------
#define SH_H 0
#define SH_P 16512                       // floats (== 32*516)
#define SH_TOTAL (SH_P + 8*290)          // floats
#define SMEM_BYTES (SH_TOTAL*4 + 16)     // + two mbarriers

__global__ __launch_bounds__(256,1) __cluster_dims__(4,1,1)
void lstm_kernel(const float* __restrict__ init_states,
                 float* __restrict__ out)
{
    extern __shared__ __align__(16) float smf[];

    const int tid  = threadIdx.x;
    const int w    = tid >> 5;
    const int lane = tid & 31;
    const int gid  = lane >> 2;
    const int tig  = lane & 3;
    const int kh   = w & 3;        // k-quarter (128 k each)
    const int mt   = w >> 2;       // m-tile (16 batches each)
    const int jb   = blockIdx.x * 4;
    const int kbase = kh * 128;

    unsigned smem_u32;
    asm("{ .reg .u64 t0; cvta.to.shared.u64 t0, %1; cvt.u32.u64 %0, t0; }"
        : "=r"(smem_u32) : "l"(smf));
    const unsigned mbar0 = smem_u32 + SH_TOTAL*4;
    const unsigned mbar1 = mbar0 + 8;
    const unsigned my_wait_mbar = mt ? mbar1 : mbar0;

    unsigned rank;
    asm("mov.u32 %0, %%cluster_ctarank;" : "=r"(rank));
    const unsigned my_tma_mbar = (rank >> 1) ? mbar1 : mbar0;

    // --- preload U fragments into registers (once): ub[nt][ks][2] ---
    unsigned ub[2][16][2];
    {
        #pragma unroll
        for (int nt = 0; nt < 2; nt++) {
            const unsigned* Ucol = g_Ut + (size_t)kbase * NG + blockIdx.x*16 + nt*8 + gid;
            #pragma unroll
            for (int ks = 0; ks < 16; ks++) {
                ub[nt][ks][0] = Ucol[(size_t)(ks*8 + tig    ) * NG];
                ub[nt][ks][1] = Ucol[(size_t)(ks*8 + tig + 4) * NG];
            }
        }
    }

    // owner mapping (tid < 128): one (batch, jj) cell each
    const int o_b  = tid >> 2;     // 0..31
    const int o_jj = tid & 3;
    const int o_mt = o_b >> 4;
    const int o_row = o_b & 15;
    float cstate = 0.f;
    if (tid < 128) cstate = init_states[Bdim*Hdim + o_b*Hdim + jb + o_jj];

    // mbarrier init + cluster sync (peers' multicast needs my mbars live)
    if (tid == 0) {
        asm volatile("mbarrier.init.shared.b64 [%0], 1;" :: "r"(mbar0) : "memory");
        asm volatile("mbarrier.init.shared.b64 [%0], 1;" :: "r"(mbar1) : "memory");
    }
    __syncthreads();
    asm volatile("barrier.cluster.arrive.aligned;" ::: "memory");
    asm volatile("barrier.cluster.wait.aligned;" ::: "memory");

    // helper: arm both halves' expect_tx and issue this CTA's slice of h[buf]
    auto issue_h_tma = [&](int buf) {
        asm volatile("mbarrier.arrive.expect_tx.shared.b64 _, [%0], %1;"
                     :: "r"(mbar0), "r"(H_HALF_BYTES) : "memory");
        asm volatile("mbarrier.arrive.expect_tx.shared.b64 _, [%0], %1;"
                     :: "r"(mbar1), "r"(H_HALF_BYTES) : "memory");
        const char* src = (const char*)(g_h[buf]) + rank * H_SLICE_BYTES;
        unsigned dst = smem_u32 + rank * H_SLICE_BYTES;
        asm volatile(
            "cp.async.bulk.shared::cluster.global.mbarrier::complete_tx::bytes.multicast::cluster "
            "[%0], [%1], %2, [%3], %4;"
            :: "r"(dst), "l"(src), "r"(H_SLICE_BYTES), "r"(my_tma_mbar),
               "h"((unsigned short)0xF) : "memory");
    };

    // prime step 0
    if (tid == 0) issue_h_tma(0);

    float hn = 0.f;   // carried for deferred out-store

    for (int t = 0; t < Tdim; t++) {
        // prefetch G (DRAM; consumed after mma+reduce) — overlaps TMA flight
        float pg0=0.f, pg1=0.f, pg2=0.f, pg3=0.f;
        if (tid < 128) {
            const float* gr = g_G + ((size_t)t * Bdim + o_b) * NG + jb + o_jj;
            pg0 = __ldcg(gr);
            pg1 = __ldcg(gr + 512);
            pg2 = __ldcg(gr + 1024);
            pg3 = __ldcg(gr + 1536);
        }

        // wait only for my half (warps mt=0: batches 0-15; mt=1: 16-31)
        {
            unsigned parity = t & 1;
            asm volatile(
                "{\n\t.reg .pred P;\n"
                "W%=:\n\t"
                "mbarrier.try_wait.parity.acquire.cta.shared::cta.b64 P, [%0], %1, 0x989680;\n\t"
                "@P bra D%=;\n\t"
                "bra W%=;\n"
                "D%=:\n\t}"
                :: "r"(my_wait_mbar), "r"(parity) : "memory");
        }

        // mma: warp tile m16 x n16, K=128; 4 sub-chains (2 nt x even/odd ks)
        float acc0[2][4], acc1[2][4];
        #pragma unroll
        for (int nt = 0; nt < 2; nt++)
            #pragma unroll
            for (int r = 0; r < 4; r++) { acc0[nt][r] = 0.f; acc1[nt][r] = 0.f; }
        {
            const int row = mt*16 + gid;
            const unsigned* hs = (const unsigned*)&smf[SH_H + row*HROW + kbase + tig];
            #pragma unroll
            for (int ks = 0; ks < 16; ks += 2) {
                unsigned afA[4], afB[4];
                afA[0] = hs[ks*8];
                afA[1] = hs[ks*8 + 8*HROW];
                afA[2] = hs[ks*8 + 4];
                afA[3] = hs[ks*8 + 8*HROW + 4];
                afB[0] = hs[(ks+1)*8];
                afB[1] = hs[(ks+1)*8 + 8*HROW];
                afB[2] = hs[(ks+1)*8 + 4];
                afB[3] = hs[(ks+1)*8 + 8*HROW + 4];
                mma_tf32(acc0[0], afA, ub[0][ks]);
                mma_tf32(acc0[1], afA, ub[1][ks]);
                mma_tf32(acc1[0], afB, ub[0][ks+1]);
                mma_tf32(acc1[1], afB, ub[1][ks+1]);
            }
        }

        // stash merged partials: pbuf[w][row16][n16] (row stride 18, blk 290)
        {
            float* pb = &smf[SH_P + w*290];
            #pragma unroll
            for (int nt = 0; nt < 2; nt++) {
                *(float2*)&pb[ gid     *18 + nt*8 + 2*tig] =
                    make_float2(acc0[nt][0] + acc1[nt][0], acc0[nt][1] + acc1[nt][1]);
                *(float2*)&pb[(gid + 8)*18 + nt*8 + 2*tig] =
                    make_float2(acc0[nt][2] + acc1[nt][2], acc0[nt][3] + acc1[nt][3]);
            }
        }
        __syncthreads();

        // owners: 4-way k-reduce + G + LSTM cell; write tf32-rounded h
        if (tid < 128) {
            const float* pb = &smf[SH_P + (o_mt*4)*290 + o_row*18 + o_jj];
            float z0 = pg0, z1 = pg1, z2 = pg2, z3 = pg3;
            #pragma unroll
            for (int q = 0; q < 4; q++) {
                const float* r = pb + q*290;
                z0 += r[0];    // i
                z1 += r[4];    // f
                z2 += r[8];    // g
                z3 += r[12];   // o
            }
            float iv = sigmoid_fast(z0);
            float fv = sigmoid_fast(z1);
            float gv = tanh_fast(z2);
            float ov = sigmoid_fast(z3);
            cstate = fv * cstate + iv * gv;
            hn = ov * tanh_fast(cstate);
            g_h[(t+1) & 1][o_b*HROW + jb + o_jj] = __uint_as_float(f2tf32(hn));
        }
        __syncthreads();    // all h stores done (CTA scope)

        // ---- grid barrier: ONE fence + one atomic arrive per CTA ----
        if (tid == 0) {
            asm volatile("membar.gl;" ::: "memory");
            atomicAdd(&g_bar, 1u);
        }

        // deferred out store (full-precision hn) overlaps the barrier wait
        if (tid < 128) {
            out[((size_t)o_b * Tdim + t) * Hdim + jb + o_jj] = hn;
        }

        if (tid == 0) {
            unsigned target = (unsigned)gridDim.x * (unsigned)(t + 1);
            unsigned v;
            do {
                asm volatile("ld.acquire.gpu.global.u32 %0, [%1];"
                             : "=r"(v) : "l"(&g_bar) : "memory");
            } while (v < target);
            // issue next step's h gather IMMEDIATELY on release detection:
            // all CTAs passed the post-stash sync (SH_H reads done) and their
            // h stores are gpu-visible (fence-before-arrive + ld.acquire).
            if (t + 1 < Tdim) issue_h_tma((t + 1) & 1);
        }
        __syncthreads();
    }

    asm volatile("barrier.cluster.arrive.aligned;" ::: "memory");
    asm volatile("barrier.cluster.wait.aligned;" ::: "memory");
}

// ---------------------------------------------------------------------------
extern "C" void kernel_launch(void* const* d_in, const int* in_sizes, int n_in,
                              void* d_out, int out_size) {
    const float* X           = (const float*)d_in[0];
    const float* init_states = (const float*)d_in[1];
    const float* Wi = (const float*)d_in[2];
    const float* Ui = (const float*)d_in[3];
    const float* bi = (const float*)d_in[4];
    const float* Wf = (const float*)d_in[5];
    const float* Uf = (const float*)d_in[6];
    const float* bf = (const float*)d_in[7];
    const float* Wc = (const float*)d_in[8];
    const float* Uc = (const float*)d_in[9];
    const float* bc = (const float*)d_in[10];
    const float* Wo = (const float*)d_in[11];
    const float* Uo = (const float*)d_in[12];
    const float* bo = (const float*)d_in[13];
    float* out = (float*)d_out;

    cudaFuncSetAttribute(lstm_kernel, cudaFuncAttributeMaxDynamicSharedMemorySize,
                         SMEM_BYTES);
    cudaFuncSetAttribute(xw_mma_kernel, cudaFuncAttributeMaxDynamicSharedMemorySize,
                         XW_SMEM_BYTES);

    init_kernel<<<(Bdim*Hdim + 255)/256, 256>>>(init_states, bi, bf, bc, bo);

    prep_all_kernel<<<16384 + 1024 + 1024, 256>>>(X, Wi, Wf, Wc, Wo, Ui, Uf, Uc, Uo);

    dim3 gemm_grid((Bdim*Tdim)/128, NG/128);   // (256, 16)
    xw_mma_kernel<<<gemm_grid, 256, XW_SMEM_BYTES>>>();

    lstm_kernel<<<128, 256, SMEM_BYTES>>>(init_states, out);
}

// round 16
// speedup vs baseline: 1.2418x; 1.0341x over previous
#include <cuda_runtime.h>
#include <math.h>

#define Bdim 32
#define Tdim 1024
#define DIdim 512
#define Hdim 512
#define NG (4*Hdim)

#define HROW 516                       // padded h row (floats)
#define H_SLICE_BYTES 16512u           // 8 rows * 516 * 4 (cluster of 4)
#define H_HALF_BYTES  33024u           // 2 slices (16 rows)

// Scratch (device globals)
__device__ float    g_G[Tdim*Bdim*NG];        // [t][b][gate*512+j] = x@W + bias
__device__ unsigned g_A[Tdim*Bdim*DIdim];     // tf32(X) gathered, row m=t*32+b
__device__ unsigned g_Wt[DIdim*NG];           // tf32(W) fused [k][gate*512+c]
__device__ unsigned g_Ut[Hdim*NG];            // tf32(U) fused block-interleaved
__device__ float    g_bias[NG];
__device__ __align__(16) float g_h[2][32*HROW];  // tf32-valued h, PADDED, double-buffered
__device__ unsigned int g_bar;                // grid barrier counter
__device__ unsigned g_gprog[256];             // per-mtile xw completion (16 = done)

__device__ __forceinline__ unsigned f2tf32(float f) {
    unsigned r;
    asm("cvt.rna.tf32.f32 %0, %1;" : "=r"(r) : "f"(f));
    return r;
}

__device__ __forceinline__ void mma_tf32(float* d, const unsigned* a, const unsigned* b) {
    asm volatile(
        "mma.sync.aligned.m16n8k8.row.col.f32.tf32.tf32.f32 "
        "{%0,%1,%2,%3}, {%4,%5,%6,%7}, {%8,%9}, {%0,%1,%2,%3};"
        : "+f"(d[0]), "+f"(d[1]), "+f"(d[2]), "+f"(d[3])
        : "r"(a[0]), "r"(a[1]), "r"(a[2]), "r"(a[3]), "r"(b[0]), "r"(b[1]));
}

__device__ __forceinline__ float tanh_fast(float x) {
    float e = __expf(2.0f * x);
    return 1.0f - __fdividef(2.0f, e + 1.0f);   // inf-safe
}
__device__ __forceinline__ float sigmoid_fast(float x) {
    return __fdividef(1.0f, 1.0f + __expf(-x));
}

__device__ __forceinline__ void cp_async16(unsigned smem_dst, const void* gsrc) {
    asm volatile("cp.async.cg.shared.global [%0], [%1], 16;"
                 :: "r"(smem_dst), "l"(gsrc) : "memory");
}

#define BAR_LSTM() asm volatile("bar.sync 1, 256;" ::: "memory")
#define BAR_XW()   asm volatile("bar.sync 2, 256;" ::: "memory")

// ---------------------------------------------------------------------------
__global__ void init_kernel(const float* __restrict__ init_states,
                            const float* __restrict__ bi, const float* __restrict__ bf,
                            const float* __restrict__ bc, const float* __restrict__ bo)
{
    int i = blockIdx.x * blockDim.x + threadIdx.x;
    if (i < Bdim*Hdim) {
        int b = i >> 9, j = i & 511;
        g_h[0][b*HROW + j] = __uint_as_float(f2tf32(init_states[i]));  // tf32-rounded h0
    }
    if (i < NG) {
        int gate = i >> 9, c = i & 511;
        const float* b = (gate==0) ? bi : (gate==1) ? bf : (gate==2) ? bc : bo;
        g_bias[i] = b[c];
    }
    if (i < 256) g_gprog[i] = 0u;
    if (i == 0)  g_bar = 0u;
}

// ---------------------------------------------------------------------------
// Fused prep: blocks [0,16384) = X gather; [16384,17408) = W fuse;
// [17408,18432) = U fuse+interleave.
// ---------------------------------------------------------------------------
__global__ __launch_bounds__(256) void prep_all_kernel(
    const float* __restrict__ X,
    const float* __restrict__ Wi, const float* __restrict__ Wf,
    const float* __restrict__ Wc, const float* __restrict__ Wo,
    const float* __restrict__ Ui, const float* __restrict__ Uf,
    const float* __restrict__ Uc, const float* __restrict__ Uo)
{
    int bid = blockIdx.x;
    int tid = threadIdx.x;
    if (bid < 16384) {
        int idx = bid * 256 + tid;
        int m  = idx >> 7;
        int k4 = idx & 127;
        int b = m & 31, t = m >> 5;
        float4 v = *(const float4*)(X + ((size_t)b * Tdim + t) * DIdim + k4*4);
        uint4 o;
        o.x = f2tf32(v.x); o.y = f2tf32(v.y); o.z = f2tf32(v.z); o.w = f2tf32(v.w);
        *(uint4*)(g_A + (size_t)m * DIdim + k4*4) = o;
    } else if (bid < 17408) {
        int idx = (bid - 16384) * 256 + tid;
        int gate = idx >> 16;
        int rem  = idx & 65535;
        int k  = rem >> 7;
        int c4 = rem & 127;
        const float* W = (gate==0) ? Wi : (gate==1) ? Wf : (gate==2) ? Wc : Wo;
        float4 v = *(const float4*)(W + (size_t)k * Hdim + c4*4);
        uint4 o;
        o.x = f2tf32(v.x); o.y = f2tf32(v.y); o.z = f2tf32(v.z); o.w = f2tf32(v.w);
        *(uint4*)(g_Wt + (size_t)k * NG + gate*512 + c4*4) = o;
    } else {
        int idx = (bid - 17408) * 256 + tid;
        int gate = idx >> 16;
        int rem  = idx & 65535;
        int k  = rem >> 7;
        int jq = rem & 127;
        const float* U = (gate==0) ? Ui : (gate==1) ? Uf : (gate==2) ? Uc : Uo;
        float4 v = *(const float4*)(U + (size_t)k * Hdim + jq*4);
        uint4 o;
        o.x = f2tf32(v.x); o.y = f2tf32(v.y); o.z = f2tf32(v.z); o.w = f2tf32(v.w);
        *(uint4*)(g_Ut + (size_t)k * NG + jq*16 + gate*4) = o;
    }
}

// ---------------------------------------------------------------------------
// FUSED persistent kernel. 128 CTAs x 512 threads, clusters of 4.
//   warps 0-7  : recurrence (EXACT round-15 structure; bar.sync 1,256)
//   warps 8-15 : xw GEMM producer (round-12 128x128 cp.async pipeline;
//                bar.sync 2,256), 32 jobs/CTA in consumption order,
//                signaling g_gprog[mtile] (16 ntile jobs per mtile).
// Owners gate their G prefetch on g_gprog[t>>2]==16 (cached watermark).
// ---------------------------------------------------------------------------
#define SH_H 0
#define SH_P 16512                        // floats (== 32*516)
#define SH_TOTAL (SH_P + 8*290)           // 18832 floats
#define MBAR_OFF (SH_TOTAL*4)             // 75328
#define XW_OFF   (MBAR_OFF + 16)          // 75344 (16B aligned)

#define AS_PAD 36
#define BS_PAD 132
#define XW_STAGE_A (128*AS_PAD)
#define XW_STAGE_B (32*BS_PAD)
#define XW_STAGE   (XW_STAGE_A + XW_STAGE_B)
#define XW_BYTES   (2*XW_STAGE*4)         // 70656
#define SMEM_BYTES (XW_OFF + XW_BYTES)    // 146000

__global__ __launch_bounds__(512,1) __cluster_dims__(4,1,1)
void lstm_fused_kernel(const float* __restrict__ init_states,
                       float* __restrict__ out)
{
    extern __shared__ __align__(16) float smf[];

    const int tid = threadIdx.x;
    unsigned smem_u32;
    asm("{ .reg .u64 t0; cvta.to.shared.u64 t0, %1; cvt.u32.u64 %0, t0; }"
        : "=r"(smem_u32) : "l"(smf));
    const unsigned mbar0 = smem_u32 + MBAR_OFF;
    const unsigned mbar1 = mbar0 + 8;

    unsigned rank;
    asm("mov.u32 %0, %%cluster_ctarank;" : "=r"(rank));

    // init (all 512 threads participate in these syncs)
    if (tid == 0) {
        asm volatile("mbarrier.init.shared.b64 [%0], 1;" :: "r"(mbar0) : "memory");
        asm volatile("mbarrier.init.shared.b64 [%0], 1;" :: "r"(mbar1) : "memory");
    }
    __syncthreads();
    asm volatile("barrier.cluster.arrive.aligned;" ::: "memory");
    asm volatile("barrier.cluster.wait.aligned;" ::: "memory");

    if (tid < 256) {
        // =================== RECURRENCE WARPS (0-7) ===================
        const int w    = tid >> 5;
        const int lane = tid & 31;
        const int gid  = lane >> 2;
        const int tig  = lane & 3;
        const int kh   = w & 3;
        const int mt   = w >> 2;
        const int jb   = blockIdx.x * 4;
        const int kbase = kh * 128;
        const unsigned my_wait_mbar = mt ? mbar1 : mbar0;
        const unsigned my_tma_mbar  = (rank >> 1) ? mbar1 : mbar0;

        // preload U fragments (once)
        unsigned ub[2][16][2];
        #pragma unroll
        for (int nt = 0; nt < 2; nt++) {
            const unsigned* Ucol = g_Ut + (size_t)kbase * NG + blockIdx.x*16 + nt*8 + gid;
            #pragma unroll
            for (int ks = 0; ks < 16; ks++) {
                ub[nt][ks][0] = Ucol[(size_t)(ks*8 + tig    ) * NG];
                ub[nt][ks][1] = Ucol[(size_t)(ks*8 + tig + 4) * NG];
            }
        }

        const int o_b  = tid >> 2;
        const int o_jj = tid & 3;
        const int o_mt = o_b >> 4;
        const int o_row = o_b & 15;
        float cstate = 0.f;
        if (tid < 128) cstate = init_states[Bdim*Hdim + o_b*Hdim + jb + o_jj];

        auto issue_h_tma = [&](int buf) {
            asm volatile("mbarrier.arrive.expect_tx.shared.b64 _, [%0], %1;"
                         :: "r"(mbar0), "r"(H_HALF_BYTES) : "memory");
            asm volatile("mbarrier.arrive.expect_tx.shared.b64 _, [%0], %1;"
                         :: "r"(mbar1), "r"(H_HALF_BYTES) : "memory");
            const char* src = (const char*)(g_h[buf]) + rank * H_SLICE_BYTES;
            unsigned dst = smem_u32 + rank * H_SLICE_BYTES;
            asm volatile(
                "cp.async.bulk.shared::cluster.global.mbarrier::complete_tx::bytes.multicast::cluster "
                "[%0], [%1], %2, [%3], %4;"
                :: "r"(dst), "l"(src), "r"(H_SLICE_BYTES), "r"(my_tma_mbar),
                   "h"((unsigned short)0xF) : "memory");
        };

        if (tid == 0) issue_h_tma(0);

        float hn = 0.f;
        int last_done = -1;   // highest G mtile known complete

        for (int t = 0; t < Tdim; t++) {
            // gate on xw producer progress, then prefetch G
            float pg0=0.f, pg1=0.f, pg2=0.f, pg3=0.f;
            if (tid < 128) {
                int need = t >> 2;
                if (need > last_done) {
                    unsigned v;
                    do {
                        asm volatile("ld.acquire.gpu.global.u32 %0, [%1];"
                                     : "=r"(v) : "l"(&g_gprog[need]) : "memory");
                    } while (v < 16u);
                    last_done = need;
                }
                const float* gr = g_G + ((size_t)t * Bdim + o_b) * NG + jb + o_jj;
                pg0 = __ldcg(gr);
                pg1 = __ldcg(gr + 512);
                pg2 = __ldcg(gr + 1024);
                pg3 = __ldcg(gr + 1536);
            }

            // wait for my half of h
            {
                unsigned parity = t & 1;
                asm volatile(
                    "{\n\t.reg .pred P;\n"
                    "W%=:\n\t"
                    "mbarrier.try_wait.parity.acquire.cta.shared::cta.b64 P, [%0], %1, 0x989680;\n\t"
                    "@P bra D%=;\n\t"
                    "bra W%=;\n"
                    "D%=:\n\t}"
                    :: "r"(my_wait_mbar), "r"(parity) : "memory");
            }

            // mma: m16 x n16, K=128; 4 sub-chains
            float acc0[2][4], acc1[2][4];
            #pragma unroll
            for (int nt = 0; nt < 2; nt++)
                #pragma unroll
                for (int r = 0; r < 4; r++) { acc0[nt][r] = 0.f; acc1[nt][r] = 0.f; }
            {
                const int row = mt*16 + gid;
                const unsigned* hs = (const unsigned*)&smf[SH_H + row*HROW + kbase + tig];
                #pragma unroll
                for (int ks = 0; ks < 16; ks += 2) {
                    unsigned afA[4], afB[4];
                    afA[0] = hs[ks*8];
                    afA[1] = hs[ks*8 + 8*HROW];
                    afA[2] = hs[ks*8 + 4];
                    afA[3] = hs[ks*8 + 8*HROW + 4];
                    afB[0] = hs[(ks+1)*8];
                    afB[1] = hs[(ks+1)*8 + 8*HROW];
                    afB[2] = hs[(ks+1)*8 + 4];
                    afB[3] = hs[(ks+1)*8 + 8*HROW + 4];
                    mma_tf32(acc0[0], afA, ub[0][ks]);
                    mma_tf32(acc0[1], afA, ub[1][ks]);
                    mma_tf32(acc1[0], afB, ub[0][ks+1]);
                    mma_tf32(acc1[1], afB, ub[1][ks+1]);
                }
            }

            // stash merged partials
            {
                float* pb = &smf[SH_P + w*290];
                #pragma unroll
                for (int nt = 0; nt < 2; nt++) {
                    *(float2*)&pb[ gid     *18 + nt*8 + 2*tig] =
                        make_float2(acc0[nt][0] + acc1[nt][0], acc0[nt][1] + acc1[nt][1]);
                    *(float2*)&pb[(gid + 8)*18 + nt*8 + 2*tig] =
                        make_float2(acc0[nt][2] + acc1[nt][2], acc0[nt][3] + acc1[nt][3]);
                }
            }
            BAR_LSTM();

            // owners: k-reduce + G + LSTM cell; write tf32-rounded h
            if (tid < 128) {
                const float* pb = &smf[SH_P + (o_mt*4)*290 + o_row*18 + o_jj];
                float z0 = pg0, z1 = pg1, z2 = pg2, z3 = pg3;
                #pragma unroll
                for (int q = 0; q < 4; q++) {
                    const float* r = pb + q*290;
                    z0 += r[0];
                    z1 += r[4];
                    z2 += r[8];
                    z3 += r[12];
                }
                float iv = sigmoid_fast(z0);
                float fv = sigmoid_fast(z1);
                float gv = tanh_fast(z2);
                float ov = sigmoid_fast(z3);
                cstate = fv * cstate + iv * gv;
                hn = ov * tanh_fast(cstate);
                g_h[(t+1) & 1][o_b*HROW + jb + o_jj] = __uint_as_float(f2tf32(hn));
            }
            BAR_LSTM();

            // grid barrier: one fence + one atomic arrive per CTA
            if (tid == 0) {
                asm volatile("membar.gl;" ::: "memory");
                atomicAdd(&g_bar, 1u);
            }
            if (tid < 128) {
                out[((size_t)o_b * Tdim + t) * Hdim + jb + o_jj] = hn;
            }
            if (tid == 0) {
                unsigned target = (unsigned)gridDim.x * (unsigned)(t + 1);
                unsigned v;
                do {
                    asm volatile("ld.acquire.gpu.global.u32 %0, [%1];"
                                 : "=r"(v) : "l"(&g_bar) : "memory");
                } while (v < target);
                if (t + 1 < Tdim) issue_h_tma((t + 1) & 1);
            }
            BAR_LSTM();
        }
    } else {
        // =================== XW PRODUCER WARPS (8-15) ===================
        const int tid2 = tid - 256;
        const int wid  = tid2 >> 5;
        const int lane = tid2 & 31;
        const int gid  = lane >> 2;
        const int tig  = lane & 3;
        const int warp_m = (wid & 3) * 32;
        const int warp_n = (wid >> 2) * 64;

        const unsigned xw_base = smem_u32 + XW_OFF;

        const int a_row[4] = { (tid2)>>3, (tid2+256)>>3, (tid2+512)>>3, (tid2+768)>>3 };
        const int a_k4  = (tid2 & 7) * 4;
        const int b_krow[4] = { tid2>>5, (tid2+256)>>5, (tid2+512)>>5, (tid2+768)>>5 };
        const int b_n4  = (tid2 & 31) * 4;

        for (int job = blockIdx.x; job < 4096; job += 128) {
            const int mbase = (job >> 4) * 128;
            const int nbase = (job & 15) * 128;

            auto issue_chunk = [&](int k0, int s) {
                unsigned base = xw_base + s * XW_STAGE * 4;
                #pragma unroll
                for (int r = 0; r < 4; r++) {
                    const void* src = g_A + (size_t)(mbase + a_row[r]) * DIdim + k0 + a_k4;
                    cp_async16(base + (a_row[r]*AS_PAD + a_k4)*4, src);
                }
                #pragma unroll
                for (int r = 0; r < 4; r++) {
                    const void* src = g_Wt + (size_t)(k0 + b_krow[r]) * NG + nbase + b_n4;
                    cp_async16(base + (XW_STAGE_A + b_krow[r]*BS_PAD + b_n4)*4, src);
                }
                asm volatile("cp.async.commit_group;" ::: "memory");
            };

            float acc[2][8][4];
            #pragma unroll
            for (int mt = 0; mt < 2; mt++)
                #pragma unroll
                for (int nt = 0; nt < 8; nt++)
                    #pragma unroll
                    for (int r = 0; r < 4; r++) acc[mt][nt][r] = 0.f;

            issue_chunk(0, 0);

            for (int i = 0; i < 16; i++) {
                if (i < 15) {
                    issue_chunk((i+1)*32, (i+1) & 1);
                    asm volatile("cp.async.wait_group 1;" ::: "memory");
                } else {
                    asm volatile("cp.async.wait_group 0;" ::: "memory");
                }
                BAR_XW();

                const unsigned* As = (const unsigned*)smf + XW_OFF/4 + (i & 1) * XW_STAGE;
                const unsigned* Bs = As + XW_STAGE_A;

                #pragma unroll
                for (int ks = 0; ks < 4; ks++) {
                    const int k8 = ks * 8;
                    unsigned af[2][4];
                    #pragma unroll
                    for (int mt = 0; mt < 2; mt++) {
                        int row = warp_m + mt*16 + gid;
                        af[mt][0] = As[(row    ) * AS_PAD + k8 + tig    ];
                        af[mt][1] = As[(row + 8) * AS_PAD + k8 + tig    ];
                        af[mt][2] = As[(row    ) * AS_PAD + k8 + tig + 4];
                        af[mt][3] = As[(row + 8) * AS_PAD + k8 + tig + 4];
                    }
                    unsigned bf2[8][2];
                    #pragma unroll
                    for (int nt = 0; nt < 8; nt++) {
                        int col = warp_n + nt*8 + gid;
                        bf2[nt][0] = Bs[(k8 + tig    ) * BS_PAD + col];
                        bf2[nt][1] = Bs[(k8 + tig + 4) * BS_PAD + col];
                    }
                    #pragma unroll
                    for (int mt = 0; mt < 2; mt++)
                        #pragma unroll
                        for (int nt = 0; nt < 8; nt++)
                            mma_tf32(acc[mt][nt], af[mt], bf2[nt]);
                }
                BAR_XW();
            }

            #pragma unroll
            for (int mt = 0; mt < 2; mt++) {
                #pragma unroll
                for (int nt = 0; nt < 8; nt++) {
                    int col = nbase + warp_n + nt*8 + 2*tig;
                    float b0 = g_bias[col];
                    float b1 = g_bias[col + 1];
                    int row0 = mbase + warp_m + mt*16 + gid;
                    float2 o0 = make_float2(acc[mt][nt][0] + b0, acc[mt][nt][1] + b1);
                    float2 o1 = make_float2(acc[mt][nt][2] + b0, acc[mt][nt][3] + b1);
                    *(float2*)(g_G + (size_t)row0 * NG + col)       = o0;
                    *(float2*)(g_G + (size_t)(row0 + 8) * NG + col) = o1;
                }
            }

            // signal: all stores visible, then bump this mtile's counter
            BAR_XW();
            if (tid2 == 0) {
                asm volatile("membar.gl;" ::: "memory");
                atomicAdd(&g_gprog[job >> 4], 1u);
            }
        }
    }

    // converge all 512 threads before cluster teardown
    __syncthreads();
    asm volatile("barrier.cluster.arrive.aligned;" ::: "memory");
    asm volatile("barrier.cluster.wait.aligned;" ::: "memory");
}

// ---------------------------------------------------------------------------
extern "C" void kernel_launch(void* const* d_in, const int* in_sizes, int n_in,
                              void* d_out, int out_size) {
    const float* X           = (const float*)d_in[0];
    const float* init_states = (const float*)d_in[1];
    const float* Wi = (const float*)d_in[2];
    const float* Ui = (const float*)d_in[3];
    const float* bi = (const float*)d_in[4];
    const float* Wf = (const float*)d_in[5];
    const float* Uf = (const float*)d_in[6];
    const float* bf = (const float*)d_in[7];
    const float* Wc = (const float*)d_in[8];
    const float* Uc = (const float*)d_in[9];
    const float* bc = (const float*)d_in[10];
    const float* Wo = (const float*)d_in[11];
    const float* Uo = (const float*)d_in[12];
    const float* bo = (const float*)d_in[13];
    float* out = (float*)d_out;

    cudaFuncSetAttribute(lstm_fused_kernel, cudaFuncAttributeMaxDynamicSharedMemorySize,
                         SMEM_BYTES);

    init_kernel<<<(Bdim*Hdim + 255)/256, 256>>>(init_states, bi, bf, bc, bo);

    prep_all_kernel<<<16384 + 1024 + 1024, 256>>>(X, Wi, Wf, Wc, Wo, Ui, Uf, Uc, Uo);

    lstm_fused_kernel<<<128, 512, SMEM_BYTES>>>(init_states, out);
}

// round 17
// speedup vs baseline: 1.2652x; 1.0189x over previous
#include <cuda_runtime.h>
#include <math.h>

#define Bdim 32
#define Tdim 1024
#define DIdim 512
#define Hdim 512
#define NG (4*Hdim)

#define HROW 516                       // padded h row (floats)
#define H_SLICE_BYTES 16512u           // 8 rows * 516 * 4 (cluster of 4)
#define H_HALF_BYTES  33024u           // 2 slices (16 rows)

// Scratch (device globals)
__device__ float    g_G[Tdim*Bdim*NG];        // [t][b][gate*512+j] = x@W + bias
__device__ unsigned g_Wt[DIdim*NG];           // tf32(W) fused [k][gate*512+c]
__device__ unsigned g_Ut[Hdim*NG];            // tf32(U) fused block-interleaved
__device__ float    g_bias[NG];
__device__ __align__(16) float g_h[2][32*HROW];  // tf32-valued h, PADDED, double-buffered
__device__ unsigned int g_bar;                // grid barrier counter
__device__ unsigned g_gprog[256];             // per-mtile xw completion (16 = done)

__device__ __forceinline__ unsigned f2tf32(float f) {
    unsigned r;
    asm("cvt.rna.tf32.f32 %0, %1;" : "=r"(r) : "f"(f));
    return r;
}

__device__ __forceinline__ void mma_tf32(float* d, const unsigned* a, const unsigned* b) {
    asm volatile(
        "mma.sync.aligned.m16n8k8.row.col.f32.tf32.tf32.f32 "
        "{%0,%1,%2,%3}, {%4,%5,%6,%7}, {%8,%9}, {%0,%1,%2,%3};"
        : "+f"(d[0]), "+f"(d[1]), "+f"(d[2]), "+f"(d[3])
        : "r"(a[0]), "r"(a[1]), "r"(a[2]), "r"(a[3]), "r"(b[0]), "r"(b[1]));
}

__device__ __forceinline__ float tanh_fast(float x) {
    float e = __expf(2.0f * x);
    return 1.0f - __fdividef(2.0f, e + 1.0f);   // inf-safe
}
__device__ __forceinline__ float sigmoid_fast(float x) {
    return __fdividef(1.0f, 1.0f + __expf(-x));
}

__device__ __forceinline__ void cp_async16(unsigned smem_dst, const void* gsrc) {
    asm volatile("cp.async.cg.shared.global [%0], [%1], 16;"
                 :: "r"(smem_dst), "l"(gsrc) : "memory");
}

#define BAR_LSTM() asm volatile("bar.sync 1, 256;" ::: "memory")
#define BAR_XW()   asm volatile("bar.sync 2, 256;" ::: "memory")

// ---------------------------------------------------------------------------
__global__ void init_kernel(const float* __restrict__ init_states,
                            const float* __restrict__ bi, const float* __restrict__ bf,
                            const float* __restrict__ bc, const float* __restrict__ bo)
{
    int i = blockIdx.x * blockDim.x + threadIdx.x;
    if (i < Bdim*Hdim) {
        int b = i >> 9, j = i & 511;
        g_h[0][b*HROW + j] = __uint_as_float(f2tf32(init_states[i]));  // tf32-rounded h0
    }
    if (i < NG) {
        int gate = i >> 9, c = i & 511;
        const float* b = (gate==0) ? bi : (gate==1) ? bf : (gate==2) ? bc : bo;
        g_bias[i] = b[c];
    }
    if (i < 256) g_gprog[i] = 0u;
    if (i == 0)  g_bar = 0u;
}

// ---------------------------------------------------------------------------
// Prep (W/U only — X conversion now inlined in the producer warps):
// blocks [0,1024) = W fuse; [1024,2048) = U fuse+interleave.
// ---------------------------------------------------------------------------
__global__ __launch_bounds__(256) void prep_wu_kernel(
    const float* __restrict__ Wi, const float* __restrict__ Wf,
    const float* __restrict__ Wc, const float* __restrict__ Wo,
    const float* __restrict__ Ui, const float* __restrict__ Uf,
    const float* __restrict__ Uc, const float* __restrict__ Uo)
{
    int bid = blockIdx.x;
    int tid = threadIdx.x;
    if (bid < 1024) {
        int idx = bid * 256 + tid;
        int gate = idx >> 16;
        int rem  = idx & 65535;
        int k  = rem >> 7;
        int c4 = rem & 127;
        const float* W = (gate==0) ? Wi : (gate==1) ? Wf : (gate==2) ? Wc : Wo;
        float4 v = *(const float4*)(W + (size_t)k * Hdim + c4*4);
        uint4 o;
        o.x = f2tf32(v.x); o.y = f2tf32(v.y); o.z = f2tf32(v.z); o.w = f2tf32(v.w);
        *(uint4*)(g_Wt + (size_t)k * NG + gate*512 + c4*4) = o;
    } else {
        int idx = (bid - 1024) * 256 + tid;
        int gate = idx >> 16;
        int rem  = idx & 65535;
        int k  = rem >> 7;
        int jq = rem & 127;
        const float* U = (gate==0) ? Ui : (gate==1) ? Uf : (gate==2) ? Uc : Uo;
        float4 v = *(const float4*)(U + (size_t)k * Hdim + jq*4);
        uint4 o;
        o.x = f2tf32(v.x); o.y = f2tf32(v.y); o.z = f2tf32(v.z); o.w = f2tf32(v.w);
        *(uint4*)(g_Ut + (size_t)k * NG + jq*16 + gate*4) = o;
    }
}

// ---------------------------------------------------------------------------
// FUSED persistent kernel. 128 CTAs x 512 threads, clusters of 4.
//   warps 0-7  : recurrence (EXACT round-15 structure; bar.sync 1,256)
//   warps 8-15 : xw GEMM producer; A staged straight from X (LDG float4 ->
//                cvt.rna.tf32 -> STS; loads for chunk i+1 issued into regs at
//                the top of iteration i, stored after the mma so LDG latency
//                hides under wait_group+HMMA). B stays cp.async. G bitwise
//                identical to the prep_x path (same cvt, same fragment maps).
// ---------------------------------------------------------------------------
#define SH_H 0
#define SH_P 16512                        // floats (== 32*516)
#define SH_TOTAL (SH_P + 8*290)           // 18832 floats
#define MBAR_OFF (SH_TOTAL*4)             // 75328
#define XW_OFF   (MBAR_OFF + 16)          // 75344 (16B aligned)

#define AS_PAD 36
#define BS_PAD 132
#define XW_STAGE_A (128*AS_PAD)
#define XW_STAGE_B (32*BS_PAD)
#define XW_STAGE   (XW_STAGE_A + XW_STAGE_B)
#define XW_BYTES   (2*XW_STAGE*4)         // 70656
#define SMEM_BYTES (XW_OFF + XW_BYTES)    // 146000

__global__ __launch_bounds__(512,1) __cluster_dims__(4,1,1)
void lstm_fused_kernel(const float* __restrict__ X,
                       const float* __restrict__ init_states,
                       float* __restrict__ out)
{
    extern __shared__ __align__(16) float smf[];

    const int tid = threadIdx.x;
    unsigned smem_u32;
    asm("{ .reg .u64 t0; cvta.to.shared.u64 t0, %1; cvt.u32.u64 %0, t0; }"
        : "=r"(smem_u32) : "l"(smf));
    const unsigned mbar0 = smem_u32 + MBAR_OFF;
    const unsigned mbar1 = mbar0 + 8;

    unsigned rank;
    asm("mov.u32 %0, %%cluster_ctarank;" : "=r"(rank));

    if (tid == 0) {
        asm volatile("mbarrier.init.shared.b64 [%0], 1;" :: "r"(mbar0) : "memory");
        asm volatile("mbarrier.init.shared.b64 [%0], 1;" :: "r"(mbar1) : "memory");
    }
    __syncthreads();
    asm volatile("barrier.cluster.arrive.aligned;" ::: "memory");
    asm volatile("barrier.cluster.wait.aligned;" ::: "memory");

    if (tid < 256) {
        // =================== RECURRENCE WARPS (0-7) ===================
        const int w    = tid >> 5;
        const int lane = tid & 31;
        const int gid  = lane >> 2;
        const int tig  = lane & 3;
        const int kh   = w & 3;
        const int mt   = w >> 2;
        const int jb   = blockIdx.x * 4;
        const int kbase = kh * 128;
        const unsigned my_wait_mbar = mt ? mbar1 : mbar0;
        const unsigned my_tma_mbar  = (rank >> 1) ? mbar1 : mbar0;

        unsigned ub[2][16][2];
        #pragma unroll
        for (int nt = 0; nt < 2; nt++) {
            const unsigned* Ucol = g_Ut + (size_t)kbase * NG + blockIdx.x*16 + nt*8 + gid;
            #pragma unroll
            for (int ks = 0; ks < 16; ks++) {
                ub[nt][ks][0] = Ucol[(size_t)(ks*8 + tig    ) * NG];
                ub[nt][ks][1] = Ucol[(size_t)(ks*8 + tig + 4) * NG];
            }
        }

        const int o_b  = tid >> 2;
        const int o_jj = tid & 3;
        const int o_mt = o_b >> 4;
        const int o_row = o_b & 15;
        float cstate = 0.f;
        if (tid < 128) cstate = init_states[Bdim*Hdim + o_b*Hdim + jb + o_jj];

        auto issue_h_tma = [&](int buf) {
            asm volatile("mbarrier.arrive.expect_tx.shared.b64 _, [%0], %1;"
                         :: "r"(mbar0), "r"(H_HALF_BYTES) : "memory");
            asm volatile("mbarrier.arrive.expect_tx.shared.b64 _, [%0], %1;"
                         :: "r"(mbar1), "r"(H_HALF_BYTES) : "memory");
            const char* src = (const char*)(g_h[buf]) + rank * H_SLICE_BYTES;
            unsigned dst = smem_u32 + rank * H_SLICE_BYTES;
            asm volatile(
                "cp.async.bulk.shared::cluster.global.mbarrier::complete_tx::bytes.multicast::cluster "
                "[%0], [%1], %2, [%3], %4;"
                :: "r"(dst), "l"(src), "r"(H_SLICE_BYTES), "r"(my_tma_mbar),
                   "h"((unsigned short)0xF) : "memory");
        };

        if (tid == 0) issue_h_tma(0);

        float hn = 0.f;
        int last_done = -1;

        for (int t = 0; t < Tdim; t++) {
            float pg0=0.f, pg1=0.f, pg2=0.f, pg3=0.f;
            if (tid < 128) {
                int need = t >> 2;
                if (need > last_done) {
                    unsigned v;
                    do {
                        asm volatile("ld.acquire.gpu.global.u32 %0, [%1];"
                                     : "=r"(v) : "l"(&g_gprog[need]) : "memory");
                    } while (v < 16u);
                    last_done = need;
                }
                const float* gr = g_G + ((size_t)t * Bdim + o_b) * NG + jb + o_jj;
                pg0 = __ldcg(gr);
                pg1 = __ldcg(gr + 512);
                pg2 = __ldcg(gr + 1024);
                pg3 = __ldcg(gr + 1536);
            }

            {
                unsigned parity = t & 1;
                asm volatile(
                    "{\n\t.reg .pred P;\n"
                    "W%=:\n\t"
                    "mbarrier.try_wait.parity.acquire.cta.shared::cta.b64 P, [%0], %1, 0x989680;\n\t"
                    "@P bra D%=;\n\t"
                    "bra W%=;\n"
                    "D%=:\n\t}"
                    :: "r"(my_wait_mbar), "r"(parity) : "memory");
            }

            float acc0[2][4], acc1[2][4];
            #pragma unroll
            for (int nt = 0; nt < 2; nt++)
                #pragma unroll
                for (int r = 0; r < 4; r++) { acc0[nt][r] = 0.f; acc1[nt][r] = 0.f; }
            {
                const int row = mt*16 + gid;
                const unsigned* hs = (const unsigned*)&smf[SH_H + row*HROW + kbase + tig];
                #pragma unroll
                for (int ks = 0; ks < 16; ks += 2) {
                    unsigned afA[4], afB[4];
                    afA[0] = hs[ks*8];
                    afA[1] = hs[ks*8 + 8*HROW];
                    afA[2] = hs[ks*8 + 4];
                    afA[3] = hs[ks*8 + 8*HROW + 4];
                    afB[0] = hs[(ks+1)*8];
                    afB[1] = hs[(ks+1)*8 + 8*HROW];
                    afB[2] = hs[(ks+1)*8 + 4];
                    afB[3] = hs[(ks+1)*8 + 8*HROW + 4];
                    mma_tf32(acc0[0], afA, ub[0][ks]);
                    mma_tf32(acc0[1], afA, ub[1][ks]);
                    mma_tf32(acc1[0], afB, ub[0][ks+1]);
                    mma_tf32(acc1[1], afB, ub[1][ks+1]);
                }
            }

            {
                float* pb = &smf[SH_P + w*290];
                #pragma unroll
                for (int nt = 0; nt < 2; nt++) {
                    *(float2*)&pb[ gid     *18 + nt*8 + 2*tig] =
                        make_float2(acc0[nt][0] + acc1[nt][0], acc0[nt][1] + acc1[nt][1]);
                    *(float2*)&pb[(gid + 8)*18 + nt*8 + 2*tig] =
                        make_float2(acc0[nt][2] + acc1[nt][2], acc0[nt][3] + acc1[nt][3]);
                }
            }
            BAR_LSTM();

            if (tid < 128) {
                const float* pb = &smf[SH_P + (o_mt*4)*290 + o_row*18 + o_jj];
                float z0 = pg0, z1 = pg1, z2 = pg2, z3 = pg3;
                #pragma unroll
                for (int q = 0; q < 4; q++) {
                    const float* r = pb + q*290;
                    z0 += r[0];
                    z1 += r[4];
                    z2 += r[8];
                    z3 += r[12];
                }
                float iv = sigmoid_fast(z0);
                float fv = sigmoid_fast(z1);
                float gv = tanh_fast(z2);
                float ov = sigmoid_fast(z3);
                cstate = fv * cstate + iv * gv;
                hn = ov * tanh_fast(cstate);
                g_h[(t+1) & 1][o_b*HROW + jb + o_jj] = __uint_as_float(f2tf32(hn));
            }
            BAR_LSTM();

            if (tid == 0) {
                asm volatile("membar.gl;" ::: "memory");
                atomicAdd(&g_bar, 1u);
            }
            if (tid < 128) {
                out[((size_t)o_b * Tdim + t) * Hdim + jb + o_jj] = hn;
            }
            if (tid == 0) {
                unsigned target = (unsigned)gridDim.x * (unsigned)(t + 1);
                unsigned v;
                do {
                    asm volatile("ld.acquire.gpu.global.u32 %0, [%1];"
                                 : "=r"(v) : "l"(&g_bar) : "memory");
                } while (v < target);
                if (t + 1 < Tdim) issue_h_tma((t + 1) & 1);
            }
            BAR_LSTM();
        }
    } else {
        // =================== XW PRODUCER WARPS (8-15) ===================
        const int tid2 = tid - 256;
        const int wid  = tid2 >> 5;
        const int lane = tid2 & 31;
        const int gid  = lane >> 2;
        const int tig  = lane & 3;
        const int warp_m = (wid & 3) * 32;
        const int warp_n = (wid >> 2) * 64;

        const unsigned xw_base = smem_u32 + XW_OFF;

        const int a_row[4] = { (tid2)>>3, (tid2+256)>>3, (tid2+512)>>3, (tid2+768)>>3 };
        const int a_k4  = (tid2 & 7) * 4;
        const int b_krow[4] = { tid2>>5, (tid2+256)>>5, (tid2+512)>>5, (tid2+768)>>5 };
        const int b_n4  = (tid2 & 31) * 4;

        for (int job = blockIdx.x; job < 4096; job += 128) {
            const int mbase = (job >> 4) * 128;
            const int nbase = (job & 15) * 128;

            // per-thread X row pointers for this mtile (row m = t*32 + b)
            const float* xsrc[4];
            #pragma unroll
            for (int r = 0; r < 4; r++) {
                int row = mbase + a_row[r];
                int b = row & 31, tt = row >> 5;
                xsrc[r] = X + ((size_t)b * Tdim + tt) * DIdim + a_k4;
            }

            auto ldA = [&](int k0, float4* regs) {
                #pragma unroll
                for (int r = 0; r < 4; r++) regs[r] = __ldg((const float4*)(xsrc[r] + k0));
            };
            auto stA = [&](const float4* regs, int s) {
                unsigned* As_st = (unsigned*)smf + XW_OFF/4 + s * XW_STAGE;
                #pragma unroll
                for (int r = 0; r < 4; r++) {
                    uint4 o;
                    o.x = f2tf32(regs[r].x); o.y = f2tf32(regs[r].y);
                    o.z = f2tf32(regs[r].z); o.w = f2tf32(regs[r].w);
                    *(uint4*)&As_st[a_row[r]*AS_PAD + a_k4] = o;
                }
            };
            auto issueB = [&](int k0, int s) {
                unsigned base = xw_base + s * XW_STAGE * 4;
                #pragma unroll
                for (int r = 0; r < 4; r++) {
                    const void* src = g_Wt + (size_t)(k0 + b_krow[r]) * NG + nbase + b_n4;
                    cp_async16(base + (XW_STAGE_A + b_krow[r]*BS_PAD + b_n4)*4, src);
                }
                asm volatile("cp.async.commit_group;" ::: "memory");
            };

            float acc[2][8][4];
            #pragma unroll
            for (int mt = 0; mt < 2; mt++)
                #pragma unroll
                for (int nt = 0; nt < 8; nt++)
                    #pragma unroll
                    for (int r = 0; r < 4; r++) acc[mt][nt][r] = 0.f;

            // prologue: stage chunk 0 (A sync, B async)
            {
                float4 r0[4];
                ldA(0, r0);
                stA(r0, 0);
            }
            issueB(0, 0);

            float4 anext[4];
            for (int i = 0; i < 16; i++) {
                if (i < 15) {
                    issueB((i+1)*32, (i+1) & 1);
                    ldA((i+1)*32, anext);      // LDG latency hides under wait+mma
                    asm volatile("cp.async.wait_group 1;" ::: "memory");
                } else {
                    asm volatile("cp.async.wait_group 0;" ::: "memory");
                }
                BAR_XW();

                const unsigned* As = (const unsigned*)smf + XW_OFF/4 + (i & 1) * XW_STAGE;
                const unsigned* Bs = As + XW_STAGE_A;

                #pragma unroll
                for (int ks = 0; ks < 4; ks++) {
                    const int k8 = ks * 8;
                    unsigned af[2][4];
                    #pragma unroll
                    for (int mt = 0; mt < 2; mt++) {
                        int row = warp_m + mt*16 + gid;
                        af[mt][0] = As[(row    ) * AS_PAD + k8 + tig    ];
                        af[mt][1] = As[(row + 8) * AS_PAD + k8 + tig    ];
                        af[mt][2] = As[(row    ) * AS_PAD + k8 + tig + 4];
                        af[mt][3] = As[(row + 8) * AS_PAD + k8 + tig + 4];
                    }
                    unsigned bf2[8][2];
                    #pragma unroll
                    for (int nt = 0; nt < 8; nt++) {
                        int col = warp_n + nt*8 + gid;
                        bf2[nt][0] = Bs[(k8 + tig    ) * BS_PAD + col];
                        bf2[nt][1] = Bs[(k8 + tig + 4) * BS_PAD + col];
                    }
                    #pragma unroll
                    for (int mt = 0; mt < 2; mt++)
                        #pragma unroll
                        for (int nt = 0; nt < 8; nt++)
                            mma_tf32(acc[mt][nt], af[mt], bf2[nt]);
                }

                // store next chunk's A into the other stage (read at i+1,
                // after the closing BAR; stage (i+1)&1 reads finished at
                // the BAR closing iteration i-1)
                if (i < 15) stA(anext, (i+1) & 1);

                BAR_XW();
            }

            #pragma unroll
            for (int mt = 0; mt < 2; mt++) {
                #pragma unroll
                for (int nt = 0; nt < 8; nt++) {
                    int col = nbase + warp_n + nt*8 + 2*tig;
                    float b0 = g_bias[col];
                    float b1 = g_bias[col + 1];
                    int row0 = mbase + warp_m + mt*16 + gid;
                    float2 o0 = make_float2(acc[mt][nt][0] + b0, acc[mt][nt][1] + b1);
                    float2 o1 = make_float2(acc[mt][nt][2] + b0, acc[mt][nt][3] + b1);
                    *(float2*)(g_G + (size_t)row0 * NG + col)       = o0;
                    *(float2*)(g_G + (size_t)(row0 + 8) * NG + col) = o1;
                }
            }

            BAR_XW();
            if (tid2 == 0) {
                asm volatile("membar.gl;" ::: "memory");
                atomicAdd(&g_gprog[job >> 4], 1u);
            }
        }
    }

    __syncthreads();
    asm volatile("barrier.cluster.arrive.aligned;" ::: "memory");
    asm volatile("barrier.cluster.wait.aligned;" ::: "memory");
}

// ---------------------------------------------------------------------------
extern "C" void kernel_launch(void* const* d_in, const int* in_sizes, int n_in,
                              void* d_out, int out_size) {
    const float* X           = (const float*)d_in[0];
    const float* init_states = (const float*)d_in[1];
    const float* Wi = (const float*)d_in[2];
    const float* Ui = (const float*)d_in[3];
    const float* bi = (const float*)d_in[4];
    const float* Wf = (const float*)d_in[5];
    const float* Uf = (const float*)d_in[6];
    const float* bf = (const float*)d_in[7];
    const float* Wc = (const float*)d_in[8];
    const float* Uc = (const float*)d_in[9];
    const float* bc = (const float*)d_in[10];
    const float* Wo = (const float*)d_in[11];
    const float* Uo = (const float*)d_in[12];
    const float* bo = (const float*)d_in[13];
    float* out = (float*)d_out;

    cudaFuncSetAttribute(lstm_fused_kernel, cudaFuncAttributeMaxDynamicSharedMemorySize,
                         SMEM_BYTES);

    init_kernel<<<(Bdim*Hdim + 255)/256, 256>>>(init_states, bi, bf, bc, bo);

    prep_wu_kernel<<<2048, 256>>>(Wi, Wf, Wc, Wo, Ui, Uf, Uc, Uo);

    lstm_fused_kernel<<<128, 512, SMEM_BYTES>>>(X, init_states, out);
}